// round 1
// baseline (speedup 1.0000x reference)
#include <cuda_runtime.h>

#define BATCH 32
#define NSEQ  2048
#define F     32
#define SPLITS 16
#define ROWS1 (NSEQ / SPLITS)   // 128 rows per kernel-1 block
#define ROWS2 128               // rows per kernel-2 block
#define INV_N (1.0f / 2048.0f)

// Scratch: per-(batch,split) partial M = phi^T @ u  (32x32 each).
// Every element is overwritten by kernel 1 on every launch -> deterministic.
__device__ float g_Mpart[BATCH * SPLITS * F * F];

// ---------------------------------------------------------------------------
// Kernel 1: partial M_b = sum_j phi_j (outer) u_j over a 128-row slice.
// One thread per row (row == one 128B line -> LDG.128 is line-exact).
// ---------------------------------------------------------------------------
__global__ __launch_bounds__(ROWS1) void k_partialM(
    const float* __restrict__ x,
    const float* __restrict__ w_phi, const float* __restrict__ b_phi,
    const float* __restrict__ w_u,   const float* __restrict__ b_u)
{
    __shared__ float ws_phi[F * F], ws_u[F * F];
    __shared__ float bs_phi[F], bs_u[F];
    __shared__ float phi_s[F * 129];   // f-major, pad 129 -> conflict-free
    __shared__ float u_s[F * 129];

    const int b     = blockIdx.x;
    const int split = blockIdx.y;
    const int t     = threadIdx.x;

    for (int i = t; i < F * F; i += ROWS1) {
        ws_phi[i] = w_phi[i];
        ws_u[i]   = w_u[i];
    }
    if (t < F) { bs_phi[t] = b_phi[t]; bs_u[t] = b_u[t]; }
    __syncthreads();

    // ---- Phase A: per-thread row -> phi, u ----
    const int row = split * ROWS1 + t;
    const float4* xr = (const float4*)(x + ((size_t)b * NSEQ + row) * F);
    float xv[F];
#pragma unroll
    for (int i = 0; i < 8; i++) {
        float4 v = xr[i];
        xv[4*i+0] = v.x; xv[4*i+1] = v.y; xv[4*i+2] = v.z; xv[4*i+3] = v.w;
    }

    float phi[F], uu[F];
#pragma unroll
    for (int f = 0; f < F; f++) { phi[f] = bs_phi[f]; uu[f] = bs_u[f]; }

#pragma unroll
    for (int k = 0; k < F; k++) {
        const float xk = xv[k];
#pragma unroll
        for (int f4 = 0; f4 < 8; f4++) {
            float4 wp = *(const float4*)(ws_phi + k * F + 4 * f4);
            float4 wv = *(const float4*)(ws_u   + k * F + 4 * f4);
            phi[4*f4+0] += xk * wp.x; phi[4*f4+1] += xk * wp.y;
            phi[4*f4+2] += xk * wp.z; phi[4*f4+3] += xk * wp.w;
            uu [4*f4+0] += xk * wv.x; uu [4*f4+1] += xk * wv.y;
            uu [4*f4+2] += xk * wv.z; uu [4*f4+3] += xk * wv.w;
        }
    }
#pragma unroll
    for (int f = 0; f < F; f++) {
        uu[f] = fmaxf(uu[f], 0.0f);
        phi_s[f * 129 + t] = phi[f];
        u_s  [f * 129 + t] = uu[f];
    }
    __syncthreads();

    // ---- Phase B: M[f1][f2] = sum_j phi[f1][j] * u[f2][j] ----
    const int lane = t & 31;
    const int w    = t >> 5;            // 4 warps, 8 f1-rows each
    float acc[8];
#pragma unroll
    for (int r = 0; r < 8; r++) acc[r] = 0.0f;

#pragma unroll 4
    for (int j = 0; j < ROWS1; j++) {
        const float uv = u_s[lane * 129 + j];   // stride 129 -> conflict-free
#pragma unroll
        for (int r = 0; r < 8; r++)
            acc[r] += phi_s[(w * 8 + r) * 129 + j] * uv;  // broadcast
    }

    float* mp = g_Mpart + ((size_t)(b * SPLITS + split)) * F * F;
#pragma unroll
    for (int r = 0; r < 8; r++)
        mp[(w * 8 + r) * F + lane] = acc[r];
}

// ---------------------------------------------------------------------------
// Kernel 2: out_i = ((psi_i @ M - (psi_i . phi_i) * u_i) / N) @ w_r + x_i
// One thread per row.
// ---------------------------------------------------------------------------
__global__ __launch_bounds__(ROWS2) void k_main(
    const float* __restrict__ x,
    const float* __restrict__ w_psi, const float* __restrict__ b_psi,
    const float* __restrict__ w_phi, const float* __restrict__ b_phi,
    const float* __restrict__ w_u,   const float* __restrict__ b_u,
    const float* __restrict__ w_r,
    float* __restrict__ out)
{
    __shared__ float ws_psi[F * F], ws_phi[F * F], ws_u[F * F], ws_r[F * F];
    __shared__ float Ms[F * F];
    __shared__ float bs_psi[F], bs_phi[F], bs_u[F];

    const int blk   = blockIdx.x;
    const int b     = blk / (NSEQ / ROWS2);
    const int chunk = blk % (NSEQ / ROWS2);
    const int t     = threadIdx.x;

    for (int i = t; i < F * F; i += ROWS2) {
        ws_psi[i] = w_psi[i];
        ws_phi[i] = w_phi[i];
        ws_u[i]   = w_u[i];
        ws_r[i]   = w_r[i];
        float m = 0.0f;
        const float* mp = g_Mpart + (size_t)b * SPLITS * F * F + i;
#pragma unroll
        for (int s = 0; s < SPLITS; s++) m += mp[s * F * F];
        Ms[i] = m;
    }
    if (t < F) { bs_psi[t] = b_psi[t]; bs_phi[t] = b_phi[t]; bs_u[t] = b_u[t]; }
    __syncthreads();

    const int row = chunk * ROWS2 + t;
    const size_t g = (size_t)b * NSEQ + row;
    const float4* xr = (const float4*)(x + g * F);
    float xv[F];
#pragma unroll
    for (int i = 0; i < 8; i++) {
        float4 v = xr[i];
        xv[4*i+0] = v.x; xv[4*i+1] = v.y; xv[4*i+2] = v.z; xv[4*i+3] = v.w;
    }

    // ---- psi, u ----
    float psi[F], uu[F];
#pragma unroll
    for (int f = 0; f < F; f++) { psi[f] = bs_psi[f]; uu[f] = bs_u[f]; }
#pragma unroll
    for (int k = 0; k < F; k++) {
        const float xk = xv[k];
#pragma unroll
        for (int f4 = 0; f4 < 8; f4++) {
            float4 wp = *(const float4*)(ws_psi + k * F + 4 * f4);
            float4 wv = *(const float4*)(ws_u   + k * F + 4 * f4);
            psi[4*f4+0] += xk * wp.x; psi[4*f4+1] += xk * wp.y;
            psi[4*f4+2] += xk * wp.z; psi[4*f4+3] += xk * wp.w;
            uu [4*f4+0] += xk * wv.x; uu [4*f4+1] += xk * wv.y;
            uu [4*f4+2] += xk * wv.z; uu [4*f4+3] += xk * wv.w;
        }
    }
#pragma unroll
    for (int f = 0; f < F; f++) uu[f] = fmaxf(uu[f], 0.0f);

    // ---- diag = psi . phi   via  psi.b_phi + sum_k x_k * (sum_f psi_f W_phi[k,f]) ----
    float diag = 0.0f;
#pragma unroll
    for (int f = 0; f < F; f++) diag += psi[f] * bs_phi[f];
#pragma unroll
    for (int k = 0; k < F; k++) {
        float tk0 = 0.0f, tk1 = 0.0f, tk2 = 0.0f, tk3 = 0.0f;
#pragma unroll
        for (int f4 = 0; f4 < 8; f4++) {
            float4 wp = *(const float4*)(ws_phi + k * F + 4 * f4);
            tk0 += psi[4*f4+0] * wp.x; tk1 += psi[4*f4+1] * wp.y;
            tk2 += psi[4*f4+2] * wp.z; tk3 += psi[4*f4+3] * wp.w;
        }
        diag += xv[k] * ((tk0 + tk1) + (tk2 + tk3));
    }

    // ---- o starts as residual x (frees xv) ----
    float o[F];
#pragma unroll
    for (int f = 0; f < F; f++) o[f] = xv[f];

    // ---- att[f] = (sum_k psi[k] * M[k][f] - diag * u[f]) / N ----
    float att[F];
#pragma unroll
    for (int f = 0; f < F; f++) att[f] = -diag * uu[f];
#pragma unroll
    for (int k = 0; k < F; k++) {
        const float pk = psi[k];
#pragma unroll
        for (int f4 = 0; f4 < 8; f4++) {
            float4 m = *(const float4*)(Ms + k * F + 4 * f4);
            att[4*f4+0] += pk * m.x; att[4*f4+1] += pk * m.y;
            att[4*f4+2] += pk * m.z; att[4*f4+3] += pk * m.w;
        }
    }
#pragma unroll
    for (int f = 0; f < F; f++) att[f] *= INV_N;

    // ---- o += att @ w_r ----
#pragma unroll
    for (int k = 0; k < F; k++) {
        const float ak = att[k];
#pragma unroll
        for (int f4 = 0; f4 < 8; f4++) {
            float4 wr = *(const float4*)(ws_r + k * F + 4 * f4);
            o[4*f4+0] += ak * wr.x; o[4*f4+1] += ak * wr.y;
            o[4*f4+2] += ak * wr.z; o[4*f4+3] += ak * wr.w;
        }
    }

    float4* orow = (float4*)(out + g * F);
#pragma unroll
    for (int i = 0; i < 8; i++)
        orow[i] = make_float4(o[4*i+0], o[4*i+1], o[4*i+2], o[4*i+3]);
}

// ---------------------------------------------------------------------------
extern "C" void kernel_launch(void* const* d_in, const int* in_sizes, int n_in,
                              void* d_out, int out_size)
{
    const float* x     = (const float*)d_in[0];
    const float* w_psi = (const float*)d_in[1];
    const float* b_psi = (const float*)d_in[2];
    const float* w_phi = (const float*)d_in[3];
    const float* b_phi = (const float*)d_in[4];
    const float* w_u   = (const float*)d_in[5];
    const float* b_u   = (const float*)d_in[6];
    const float* w_r   = (const float*)d_in[7];
    float* out = (float*)d_out;

    dim3 g1(BATCH, SPLITS);
    k_partialM<<<g1, ROWS1>>>(x, w_phi, b_phi, w_u, b_u);
    k_main<<<BATCH * (NSEQ / ROWS2), ROWS2>>>(x, w_psi, b_psi, w_phi, b_phi,
                                              w_u, b_u, w_r, out);
}